// round 17
// baseline (speedup 1.0000x reference)
#include <cuda_runtime.h>
#include <cstdint>

typedef unsigned long long u64;

// ---------------------------------------------------------------------------
// Packed f32x2 helpers (Blackwell packed fp32 math)
// ---------------------------------------------------------------------------
__device__ __forceinline__ u64 pack2(float a, float b) {
    u64 r;
    asm("mov.b64 %0, {%1, %2};" : "=l"(r) : "f"(a), "f"(b));
    return r;
}
__device__ __forceinline__ void unpack2(u64 v, float& a, float& b) {
    asm("mov.b64 {%0, %1}, %2;" : "=f"(a), "=f"(b) : "l"(v));
}
__device__ __forceinline__ u64 fma2(u64 a, u64 b, u64 c) {
    u64 r;
    asm("fma.rn.f32x2 %0, %1, %2, %3;" : "=l"(r) : "l"(a), "l"(b), "l"(c));
    return r;
}
__device__ __forceinline__ u64 mul2(u64 a, u64 b) {
    u64 r;
    asm("mul.rn.f32x2 %0, %1, %2;" : "=l"(r) : "l"(a), "l"(b));
    return r;
}
__device__ __forceinline__ u64 dup2(float a) {
    u64 p;
    asm("mov.b64 %0, {%1, %1};" : "=l"(p) : "f"(a));
    return p;
}

// ---------------------------------------------------------------------------
// Per-step rotation constants for sequential Ry(th0) then Rz(th1) (Bloch,
// full angles), duplicated into both f32x2 lanes. 3 x ulonglong2 per step:
//   q0 = (CB, SB), q1 = (CC, SC), q2 = (NSB, NSC)
// Read in the main kernel as 3x LDG.128 (L1-resident, uniform address).
// ---------------------------------------------------------------------------
__device__ ulonglong2 g_consts_dev[32 * 3];

__global__ void prep_consts_kernel(const float* __restrict__ theta) {
    int t = threadIdx.x;
    if (t < 32) {
        float th0 = theta[2 * t + 0];
        float th1 = theta[2 * t + 1];
        float sb = sinf(th0), cb = cosf(th0);  // Ry full angle (Bloch sphere)
        float sc = sinf(th1), cc = cosf(th1);  // Rz full angle (Bloch sphere)
        ulonglong2 q0, q1, q2;
        q0.x = dup2(cb);  q0.y = dup2(sb);
        q1.x = dup2(cc);  q1.y = dup2(sc);
        q2.x = dup2(-sb); q2.y = dup2(-sc);
        g_consts_dev[t * 3 + 0] = q0;
        g_consts_dev[t * 3 + 1] = q1;
        g_consts_dev[t * 3 + 2] = q2;
    }
}

// ---------------------------------------------------------------------------
// cp.async helpers
// ---------------------------------------------------------------------------
__device__ __forceinline__ uint32_t smem_u32(const void* p) {
    uint32_t a;
    asm("{ .reg .u64 t; cvta.to.shared.u64 t, %1; cvt.u32.u64 %0, t; }"
        : "=r"(a) : "l"(p));
    return a;
}
__device__ __forceinline__ void cp_async16(uint32_t dst, const void* src) {
    asm volatile("cp.async.cg.shared.global [%0], [%1], 16;"
                 :: "r"(dst), "l"(src) : "memory");
}

// Issue the 16 cp.async (8KB group slab) + commit. Swizzle: slot=(c+e)&7.
__device__ __forceinline__ void load_group(uint32_t slab, const float4* gbase,
                                           int lane) {
#pragma unroll
    for (int k = 0; k < 16; k++) {
        int idx = lane + k * 32;              // linear float4 index in group
        int e = idx >> 3;                     // local element 0..63
        int c = idx & 7;                      // chunk 0..7
        uint32_t dst = slab + (((e << 3) + ((c + e) & 7)) << 4);
        cp_async16(dst, gbase + idx);
    }
    asm volatile("cp.async.commit_group;" ::: "memory");
}

// ---------------------------------------------------------------------------
// Persistent warp-autonomous kernel. Each WARP independently streams
// 64-element groups (2 elements per lane, packed f32x2) through a private
// 2 x 8KB double-buffered smem slab using cp.async prefetch:
//     prefetch(g + stride) -> wait_group(1) -> compute(g)
// No __syncthreads: each warp touches only its own slab region, so DRAM
// traffic from some warps continuously overlaps compute in others.
// Math per step (identical to the validated R12 sequence):
//     r <- Rz(th1) * Ry(th0) * Rx(x_t) * r   (Bloch),  out = r.z*w + b
// ---------------------------------------------------------------------------
__global__ void __launch_bounds__(128) qsim_kernel(
    const float4* __restrict__ xg,
    const ulonglong2* __restrict__ consts,
    const float* __restrict__ w,
    const float* __restrict__ b,
    float* __restrict__ out,
    int ngroups, int stride)
{
    extern __shared__ float4 s_buf[];          // 4 warps * 2 slabs * 512 float4

    int tid  = threadIdx.x;
    int wid  = tid >> 5;
    int lane = tid & 31;

    float4* myslab = s_buf + wid * 1024;       // 2 slabs of 512 float4
    uint32_t slab_u32 = smem_u32(myslab);

    int g = blockIdx.x * 4 + wid;              // this warp's first group

    float W  = __ldg(w);
    float Bb = __ldg(b);

    if (g < ngroups)
        load_group(slab_u32, xg + (size_t)g * 512, lane);

    int buf = 0;
    const u64 NEG1 = pack2(-1.0f, -1.0f);

    for (; g < ngroups; g += stride) {
        int gn = g + stride;
        bool pf = (gn < ngroups);
        if (pf)
            load_group(slab_u32 + (buf ^ 1) * 8192, xg + (size_t)gn * 512, lane);

        if (pf) asm volatile("cp.async.wait_group 1;" ::: "memory");
        else    asm volatile("cp.async.wait_group 0;" ::: "memory");
        __syncwarp();

        const float4* s = myslab + buf * 512;
        int e0 = lane;                          // local element, lane .x
        int e1 = lane + 32;                     // local element, lane .y

        u64 rx = pack2(0.0f, 0.0f);
        u64 ry = rx;
        u64 rz = pack2(1.0f, 1.0f);

#pragma unroll
        for (int c = 0; c < 8; c++) {
            float4 a0 = s[(e0 << 3) + ((c + e0) & 7)];   // LDS.128 conflict-free
            float4 a1 = s[(e1 << 3) + ((c + e1) & 7)];
            float xa0[4] = { a0.x, a0.y, a0.z, a0.w };
            float xa1[4] = { a1.x, a1.y, a1.z, a1.w };

#pragma unroll
            for (int j = 0; j < 4; j++) {
                int t = c * 4 + j;

                float s0, c0, s1, c1;
                __sincosf(xa0[j], &s0, &c0);             // 2x MUFU
                __sincosf(xa1[j], &s1, &c1);             // 2x MUFU

                u64 sx  = pack2(s0, s1);
                u64 cx  = pack2(c0, c1);
                u64 nsx = mul2(sx, NEG1);

                ulonglong2 q0 = consts[t * 3 + 0];       // (CB, SB)  LDG.128 L1
                ulonglong2 q1 = consts[t * 3 + 1];       // (CC, SC)
                ulonglong2 q2 = consts[t * 3 + 2];       // (NSB, NSC)

                // Rx(x_t): rotate (y,z); x unchanged
                u64 y1 = fma2(cx, ry, mul2(nsx, rz));    // cx*ry - sx*rz
                u64 z1 = fma2(sx, ry, mul2(cx, rz));     // sx*ry + cx*rz

                // Ry(th0): rotate (z,x)
                u64 x2 = fma2(q0.x, rx, mul2(q0.y, z1)); // cb*rx + sb*z1
                u64 z2 = fma2(q0.x, z1, mul2(q2.x, rx)); // cb*z1 - sb*rx

                // Rz(th1): rotate (x,y)
                u64 x3 = fma2(q1.x, x2, mul2(q2.y, y1)); // cc*x2 - sc*y1
                u64 y3 = fma2(q1.x, y1, mul2(q1.y, x2)); // cc*y1 + sc*x2

                rx = x3; ry = y3; rz = z2;
            }
        }

        float z_0, z_1;
        unpack2(rz, z_0, z_1);
        size_t base = (size_t)g * 64;
        out[base + lane]      = fmaf(z_0, W, Bb);        // coalesced
        out[base + lane + 32] = fmaf(z_1, W, Bb);

        buf ^= 1;
    }
}

extern "C" void kernel_launch(void* const* d_in, const int* in_sizes, int n_in,
                              void* d_out, int out_size)
{
    const float* x     = (const float*)d_in[0];   // [B, 32]
    const float* theta = (const float*)d_in[1];   // [32, 2]
    const float* w     = (const float*)d_in[2];   // [1, 1]
    const float* b     = (const float*)d_in[3];   // [1]
    float* out = (float*)d_out;                   // [B]

    int B = in_sizes[0] / 32;
    int ngroups = B / 64;                         // 64 elements per group

    prep_consts_kernel<<<1, 32>>>(theta);

    void* consts_ptr = nullptr;
    cudaGetSymbolAddress(&consts_ptr, g_consts_dev);

    const int NBLOCKS = 444;                      // 148 SMs * 3 CTAs
    int stride = NBLOCKS * 4;                     // total warps

    const int SMEM = 4 * 2 * 8192;                // 64KB: 4 warps * 2 slabs
    cudaFuncSetAttribute(qsim_kernel, cudaFuncAttributeMaxDynamicSharedMemorySize, SMEM);

    qsim_kernel<<<NBLOCKS, 128, SMEM>>>((const float4*)x,
                                        (const ulonglong2*)consts_ptr,
                                        w, b, out, ngroups, stride);
}